// round 2
// baseline (speedup 1.0000x reference)
#include <cuda_runtime.h>

#define NT   128          // n*t
#define CH   256          // channels
#define HW   196          // h*w
#define ICN  64           // inter_channels
#define YW   224          // padded Y width
#define OUTW 448
#define MASK_ELEMS (NT*2*OUTW*OUTW)

__device__ float g_Y[NT*ICN*YW];   // padded linear output (cols >=196 garbage, never used)
__device__ float g_m[NT*HW];

// ---- packed fp32x2 helpers (FFMA2 only reachable via PTX) ----
__device__ __forceinline__ unsigned long long pk2(float lo, float hi){
    unsigned long long r; asm("mov.b64 %0,{%1,%2};" : "=l"(r) : "f"(lo),"f"(hi)); return r;
}
__device__ __forceinline__ void upk2(unsigned long long v, float& lo, float& hi){
    asm("mov.b64 {%0,%1},%2;" : "=f"(lo),"=f"(hi) : "l"(v));
}
__device__ __forceinline__ unsigned long long fma2(unsigned long long a, unsigned long long b, unsigned long long c){
    unsigned long long d; asm("fma.rn.f32x2 %0,%1,%2,%3;" : "=l"(d) : "l"(a),"l"(b),"l"(c)); return d;
}

// ---------------------------------------------------------------------------
// Kernel 1: Y[n][d][i] = sum_c Wq[d][c]*x[n][c][i]. One block/n, 224 threads,
// 8x8 register tile via FFMA2, full Wq resident in smem, pipelined x tiles.
// ---------------------------------------------------------------------------
__global__ __launch_bounds__(224) void k_linear(const float* __restrict__ x,
                                                const float* __restrict__ Wq)
{
    extern __shared__ float sm[];
    float* Ws = sm;                 // [256][64] transposed Wq
    float* Xs = sm + CH*ICN;        // [32][196] (+pad for 8-col overread)
    const int n = blockIdx.x, tid = threadIdx.x;
    const int ty = tid/28, tx = tid%28;

    for (int idx = tid; idx < CH*ICN; idx += 224) {
        int c = idx >> 6, d = idx & 63;
        Ws[idx] = Wq[d*257 + c];
    }

    const float4* xg = (const float4*)(x + (size_t)n*CH*HW); // 12544 float4, 8 tiles x 1568
    float4 pf[7];
#pragma unroll
    for (int u = 0; u < 7; u++) pf[u] = xg[tid + 224*u];

    unsigned long long acc[8][4];
#pragma unroll
    for (int r=0;r<8;r++)
#pragma unroll
        for (int p=0;p<4;p++) acc[r][p]=0ull;

    float4* Xs4 = (float4*)Xs;
    for (int t = 0; t < 8; t++) {
        __syncthreads();
#pragma unroll
        for (int u = 0; u < 7; u++) Xs4[tid + 224*u] = pf[u];
        __syncthreads();
        if (t < 7) {
#pragma unroll
            for (int u = 0; u < 7; u++) pf[u] = xg[(t+1)*1568 + tid + 224*u];
        }
        const float* wt = Ws + t*32*ICN;
#pragma unroll 4
        for (int cc = 0; cc < 32; cc++) {
            float4 a0 = *(const float4*)&wt[cc*ICN + ty*8];
            float4 a1 = *(const float4*)&wt[cc*ICN + ty*8 + 4];
            ulonglong2 b01 = *(const ulonglong2*)&Xs[cc*HW + tx*8];     // 16B aligned (784|16)
            ulonglong2 b23 = *(const ulonglong2*)&Xs[cc*HW + tx*8 + 4];
            unsigned long long bp[4] = {b01.x, b01.y, b23.x, b23.y};
            float av[8] = {a0.x,a0.y,a0.z,a0.w,a1.x,a1.y,a1.z,a1.w};
#pragma unroll
            for (int r=0;r<8;r++){
                unsigned long long ad = pk2(av[r],av[r]);
#pragma unroll
                for (int p=0;p<4;p++) acc[r][p]=fma2(ad,bp[p],acc[r][p]);
            }
        }
    }
    float* yb = g_Y + (size_t)n*ICN*YW;
#pragma unroll
    for (int r=0;r<8;r++){
        float o[8];
#pragma unroll
        for (int p=0;p<4;p++) upk2(acc[r][p], o[2*p], o[2*p+1]);
        float4* dst = (float4*)&yb[(ty*8+r)*YW + tx*8];
        dst[0] = make_float4(o[0],o[1],o[2],o[3]);
        dst[1] = make_float4(o[4],o[5],o[6],o[7]);
    }
}

// ---------------------------------------------------------------------------
// Kernel 2: fused value-linear + attention + softmax + sigmoid -> g_m.
// One block/n, 256 threads, FFMA2 score GEMM (8 rows x 8 cols per warp-chunk).
// ---------------------------------------------------------------------------
__global__ __launch_bounds__(256) void k_attn(const float* __restrict__ x,
                                              const float* __restrict__ Wq,
                                              const float* __restrict__ bq,
                                              const float* __restrict__ Wv,
                                              const float* __restrict__ bv,
                                              const float* __restrict__ lam,
                                              const int*   __restrict__ index,
                                              float*       __restrict__ vtail)
{
    extern __shared__ float sm[];
    float* qs = sm;               // [64][224] pre-scaled q
    float* ks = sm + ICN*YW;      // [64][256] zero-padded k
    float* vs = ks + ICN*256;     // [256] zero-padded v
    __shared__ float qadd[64], kadd[64];

    const int n = blockIdx.x, tid = threadIdx.x;
    const float lamv = lam[0] - 0.5f;
    const int sn = index[n>>3]*8 + (n&7);

    if (tid < 64) {
        float tt = Wq[tid*257+256]*lamv, b = bq[tid];
        qadd[tid] = b+tt; kadd[tid] = b-tt;
    }
    // value linear (from x[sn]), also the v_out tail of d_out
    if (tid < HW) {
        const float* xb = x + (size_t)sn*CH*HW + tid;
        float a0=0.f,a1=0.f,a2=0.f,a3=0.f;
#pragma unroll 4
        for (int c=0;c<CH;c+=4){
            a0=fmaf(Wv[c  ],xb[(c  )*HW],a0);
            a1=fmaf(Wv[c+1],xb[(c+1)*HW],a1);
            a2=fmaf(Wv[c+2],xb[(c+2)*HW],a2);
            a3=fmaf(Wv[c+3],xb[(c+3)*HW],a3);
        }
        float v=(a0+a1)+(a2+a3) - Wv[CH]*lamv + bv[0];
        vs[tid]=v; vtail[n*HW+tid]=v;
    } else vs[tid]=0.f;
    __syncthreads();              // qadd/kadd ready

    const float* Yq = g_Y + (size_t)n *ICN*YW;
    const float* Yk = g_Y + (size_t)sn*ICN*YW;
    for (int idx=tid; idx<ICN*YW; idx+=256){
        int d = idx/YW;
        qs[idx] = (Yq[idx] + qadd[d])*0.125f;     // fold 1/sqrt(64)
    }
    for (int idx=tid; idx<ICN*256; idx+=256){
        int d = idx>>8, j = idx&255;
        ks[idx] = (j<HW) ? (Yk[d*YW+j] + kadd[d]) : 0.f;
    }
    __syncthreads();

    const int warp = tid>>5, lane = tid&31;
    for (int it=0; it<4; it++){
        const int i0 = it*64 + warp*8;
        if (i0 >= HW) continue;                   // warp-uniform
        unsigned long long acc[8][4];
#pragma unroll
        for (int r=0;r<8;r++)
#pragma unroll
            for (int g=0;g<4;g++) acc[r][g]=0ull;

#pragma unroll 2
        for (int d=0; d<ICN; d++){
            unsigned long long kv[4];
#pragma unroll
            for (int g=0; g<4; g++)
                kv[g] = *(const unsigned long long*)&ks[d*256 + 2*lane + 64*g];
            float4 qa = *(const float4*)&qs[d*YW + i0];      // broadcast LDS.128
            float4 qb = *(const float4*)&qs[d*YW + i0 + 4];
            float qv[8]={qa.x,qa.y,qa.z,qa.w,qb.x,qb.y,qb.z,qb.w};
#pragma unroll
            for (int r=0;r<8;r++){
                unsigned long long qd = pk2(qv[r],qv[r]);
#pragma unroll
                for (int g=0;g<4;g++) acc[r][g]=fma2(qd,kv[g],acc[r][g]);
            }
        }
#pragma unroll
        for (int r=0;r<8;r++){
            const int i = i0+r;
            if (i >= HW) break;
            float s[8];
#pragma unroll
            for (int g=0;g<4;g++){
                upk2(acc[r][g], s[2*g], s[2*g+1]);
                int c0 = 2*lane + 64*g;           // even; c0<196 => both cols valid
                if (c0 >= HW) { s[2*g]=-1e30f; s[2*g+1]=-1e30f; }
            }
            float mx = s[0];
#pragma unroll
            for (int k=1;k<8;k++) mx = fmaxf(mx, s[k]);
#pragma unroll
            for (int o=16;o>0;o>>=1) mx = fmaxf(mx, __shfl_xor_sync(0xffffffffu, mx, o));
            float se=0.f, pv=0.f;
#pragma unroll
            for (int g=0;g<4;g++){
                int c0 = 2*lane + 64*g;
                float e0 = __expf(s[2*g]  -mx);
                float e1 = __expf(s[2*g+1]-mx);
                se += e0+e1;
                pv += e0*vs[c0] + e1*vs[c0+1];
            }
#pragma unroll
            for (int o=16;o>0;o>>=1){
                se += __shfl_xor_sync(0xffffffffu,se,o);
                pv += __shfl_xor_sync(0xffffffffu,pv,o);
            }
            if (lane==0) g_m[n*HW+i] = 1.f/(1.f+__expf(-(pv/se)));
        }
    }
}

// ---------------------------------------------------------------------------
// Kernel 3: 32x upsample + [1-m, m] concat. Build each contiguous 57,344-byte
// band in smem, drain with one TMA bulk store (bypasses STG issue ceiling).
// ---------------------------------------------------------------------------
__global__ __launch_bounds__(256) void k_mask(float* __restrict__ out)
{
    extern __shared__ float buf[];     // 14336 floats = 57344 B
    __shared__ float rv[14];
    const int cr  = blockIdx.x;        // cell row 0..13
    const int nc  = blockIdx.y;        // n*2+ch
    const int n   = nc>>1, ch = nc&1;
    const int tid = threadIdx.x;

    if (tid < 14){
        float m = g_m[n*HW + cr*14 + tid];
        rv[tid] = ch ? m : 1.f - m;
    }
    __syncthreads();
    float4* b4 = (float4*)buf;
#pragma unroll
    for (int u=0; u<14; u++){
        int idx  = tid + 256*u;        // 0..3583 float4s
        int col4 = idx % 112;
        float v  = rv[col4>>3];
        b4[idx] = make_float4(v,v,v,v);
    }
    __syncthreads();
    if (tid == 0){
        asm volatile("fence.proxy.async.shared::cta;" ::: "memory");
        unsigned long long gp = (unsigned long long)(out + (size_t)nc*OUTW*OUTW + (size_t)cr*32*OUTW);
        unsigned smaddr;
        asm("{ .reg .u64 t; cvta.to.shared.u64 t, %1; cvt.u32.u64 %0, t; }" : "=r"(smaddr) : "l"(buf));
        asm volatile("cp.async.bulk.global.shared::cta.bulk_group [%0], [%1], %2;"
                     :: "l"(gp), "r"(smaddr), "r"(57344) : "memory");
        asm volatile("cp.async.bulk.commit_group;" ::: "memory");
        asm volatile("cp.async.bulk.wait_group 0;" ::: "memory");
    }
}

// ---------------------------------------------------------------------------
extern "C" void kernel_launch(void* const* d_in, const int* in_sizes, int n_in,
                              void* d_out, int out_size)
{
    const float* x     = (const float*)d_in[0];
    const float* lam   = (const float*)d_in[1];
    const int*   index = (const int*)  d_in[2];
    const float* Wq    = (const float*)d_in[3];
    const float* bq    = (const float*)d_in[4];
    const float* Wv    = (const float*)d_in[5];
    const float* bv    = (const float*)d_in[6];

    float* out   = (float*)d_out;
    float* vtail = out + MASK_ELEMS;

    const int smem1 = (CH*ICN + 32*HW + 32) * (int)sizeof(float);      // 90,880 B
    const int smem2 = (ICN*YW + ICN*256 + 256) * (int)sizeof(float);   // 123,904 B
    const int smem3 = 32*OUTW*(int)sizeof(float);                      // 57,344 B
    cudaFuncSetAttribute(k_linear, cudaFuncAttributeMaxDynamicSharedMemorySize, smem1);
    cudaFuncSetAttribute(k_attn,   cudaFuncAttributeMaxDynamicSharedMemorySize, smem2);
    cudaFuncSetAttribute(k_mask,   cudaFuncAttributeMaxDynamicSharedMemorySize, smem3);

    k_linear<<<NT, 224, smem1>>>(x, Wq);
    k_attn  <<<NT, 256, smem2>>>(x, Wq, bq, Wv, bv, lam, index, vtail);
    k_mask  <<<dim3(14, 256), 256, smem3>>>(out);
}

// round 5
// speedup vs baseline: 1.2945x; 1.2945x over previous
#include <cuda_runtime.h>

#define NT   128          // n*t
#define CH   256          // channels
#define HW   196          // h*w
#define ICN  64           // inter_channels
#define YW   224          // padded Y row width
#define OUTW 448
#define MASK_ELEMS (NT*2*OUTW*OUTW)

__device__ float g_Y[NT*ICN*YW];   // linear output, cols >=196 stay zero/garbage (unused)
__device__ float g_m[NT*HW];

// ---- packed fp32x2 helpers ----
__device__ __forceinline__ unsigned long long pk2(float lo, float hi){
    unsigned long long r; asm("mov.b64 %0,{%1,%2};" : "=l"(r) : "f"(lo),"f"(hi)); return r;
}
__device__ __forceinline__ void upk2(unsigned long long v, float& lo, float& hi){
    asm("mov.b64 {%0,%1},%2;" : "=f"(lo),"=f"(hi) : "l"(v));
}
__device__ __forceinline__ unsigned long long fma2(unsigned long long a, unsigned long long b, unsigned long long c){
    unsigned long long d; asm("fma.rn.f32x2 %0,%1,%2,%3;" : "=l"(d) : "l"(a),"l"(b),"l"(c)); return d;
}

// ---------------------------------------------------------------------------
// Kernel 1: Y[n][d][i] = sum_c Wq[d][c]*x[n][c][i].
// grid (2,128): blockIdx.x = i-half (98 cols), blockIdx.y = n.
// 224 threads, 4d x 8i register tile (FFMA2), Wq resident, 2 blocks/SM.
// ---------------------------------------------------------------------------
__global__ __launch_bounds__(224, 2) void k_linear(const float* __restrict__ x,
                                                   const float* __restrict__ Wq)
{
    extern __shared__ float sm[];
    float* Ws  = sm;                    // [256][64] transposed Wq
    float* Xs0 = sm + CH*ICN;           // [32][112] x tile, buf 0
    float* Xs1 = Xs0 + 32*112;          // buf 1
    const int ih = blockIdx.x, n = blockIdx.y;
    const int tid = threadIdx.x;
    const int ty = tid / 14, tx = tid % 14;   // ty: 4 d-rows, tx: 8 i-cols
    const int d0 = ty*4, col0 = tx*8;

    for (int idx = tid; idx < CH*ICN; idx += 224) {
        int c = idx >> 6, d = idx & 63;
        Ws[idx] = Wq[d*257 + c];
    }

    // x staging: thread owns channel (tid/7) within tile, 7 float2 cols each
    const int scc = tid / 7, sjj = tid % 7;
    const float2* x2 = (const float2*)x + (size_t)n*CH*98 + ih*49;

    float* bufs[2] = {Xs0, Xs1};
    // stage tile 0
    {
        const float2* src = x2 + (size_t)scc*98;
        float2* dst = (float2*)(bufs[0] + scc*112);
#pragma unroll
        for (int u = 0; u < 7; u++) dst[sjj + 7*u] = src[sjj + 7*u];
    }
    __syncthreads();

    unsigned long long acc[4][4];
#pragma unroll
    for (int r=0;r<4;r++)
#pragma unroll
        for (int p=0;p<4;p++) acc[r][p]=0ull;

    for (int t = 0; t < 8; t++) {
        if (t < 7) {
            const float2* src = x2 + (size_t)(t*32+32+scc)*98;
            float2* dst = (float2*)(bufs[(t+1)&1] + scc*112);
#pragma unroll
            for (int u = 0; u < 7; u++) dst[sjj + 7*u] = src[sjj + 7*u];
        }
        const float* Xc = bufs[t&1];
        const float* wt = Ws + t*32*ICN;
#pragma unroll 8
        for (int cc = 0; cc < 32; cc++) {
            float4 a = *(const float4*)&wt[cc*ICN + d0];
            ulonglong2 b01 = *(const ulonglong2*)&Xc[cc*112 + col0];
            ulonglong2 b23 = *(const ulonglong2*)&Xc[cc*112 + col0 + 4];
            unsigned long long bp[4] = {b01.x, b01.y, b23.x, b23.y};
            unsigned long long a0 = pk2(a.x,a.x), a1 = pk2(a.y,a.y);
            unsigned long long a2 = pk2(a.z,a.z), a3 = pk2(a.w,a.w);
#pragma unroll
            for (int p=0;p<4;p++){
                acc[0][p]=fma2(a0,bp[p],acc[0][p]);
                acc[1][p]=fma2(a1,bp[p],acc[1][p]);
                acc[2][p]=fma2(a2,bp[p],acc[2][p]);
                acc[3][p]=fma2(a3,bp[p],acc[3][p]);
            }
        }
        __syncthreads();
    }

    float* yb = g_Y + (size_t)n*ICN*YW;
#pragma unroll
    for (int r=0;r<4;r++){
        float o[8];
#pragma unroll
        for (int p=0;p<4;p++) upk2(acc[r][p], o[2*p], o[2*p+1]);
        float* dst = &yb[(d0+r)*YW + ih*98 + col0];
#pragma unroll
        for (int k=0;k<8;k++)
            if (col0 + k < 98) dst[k] = o[k];
    }
}

// ---------------------------------------------------------------------------
// Kernel 2: fused value-linear + attention + softmax + sigmoid -> g_m.
// One block/n, 512 threads (16 warps), FFMA2 score GEMM.
// ---------------------------------------------------------------------------
__global__ __launch_bounds__(512) void k_attn(const float* __restrict__ x,
                                              const float* __restrict__ Wq,
                                              const float* __restrict__ bq,
                                              const float* __restrict__ Wv,
                                              const float* __restrict__ bv,
                                              const float* __restrict__ lam,
                                              const int*   __restrict__ index,
                                              float*       __restrict__ vtail)
{
    extern __shared__ float sm[];
    float* qs = sm;               // [64][224] pre-scaled q
    float* ks = sm + ICN*YW;      // [64][256] zero-padded k
    float* vs = ks + ICN*256;     // [256] zero-padded v
    __shared__ float qadd[64], kadd[64];

    const int n = blockIdx.x, tid = threadIdx.x;
    const float lamv = lam[0] - 0.5f;
    const int sn = index[n>>3]*8 + (n&7);

    if (tid < 64) {
        float tt = Wq[tid*257+256]*lamv, b = bq[tid];
        qadd[tid] = b+tt; kadd[tid] = b-tt;
    }
    if (tid < HW) {
        const float* xb = x + (size_t)sn*CH*HW + tid;
        float a0=0.f,a1=0.f,a2=0.f,a3=0.f;
#pragma unroll 4
        for (int c=0;c<CH;c+=4){
            a0=fmaf(Wv[c  ],xb[(c  )*HW],a0);
            a1=fmaf(Wv[c+1],xb[(c+1)*HW],a1);
            a2=fmaf(Wv[c+2],xb[(c+2)*HW],a2);
            a3=fmaf(Wv[c+3],xb[(c+3)*HW],a3);
        }
        float v=(a0+a1)+(a2+a3) - Wv[CH]*lamv + bv[0];
        vs[tid]=v; vtail[n*HW+tid]=v;
    } else if (tid < 256) vs[tid]=0.f;
    __syncthreads();

    const float* Yq = g_Y + (size_t)n *ICN*YW;
    const float* Yk = g_Y + (size_t)sn*ICN*YW;
    for (int idx=tid; idx<ICN*YW; idx+=512){
        int d = idx/YW;
        qs[idx] = (Yq[idx] + qadd[d])*0.125f;     // fold 1/sqrt(64)
    }
    for (int idx=tid; idx<ICN*256; idx+=512){
        int d = idx>>8, j = idx&255;
        ks[idx] = (j<HW) ? (Yk[d*YW+j] + kadd[d]) : 0.f;
    }
    __syncthreads();

    const int warp = tid>>5, lane = tid&31;
    for (int it=0; it<2; it++){
        const int i0 = it*128 + warp*8;
        if (i0 >= HW) continue;                   // warp-uniform
        unsigned long long acc[8][4];
#pragma unroll
        for (int r=0;r<8;r++)
#pragma unroll
            for (int g=0;g<4;g++) acc[r][g]=0ull;

#pragma unroll 2
        for (int d=0; d<ICN; d++){
            unsigned long long kv[4];
#pragma unroll
            for (int g=0; g<4; g++)
                kv[g] = *(const unsigned long long*)&ks[d*256 + 2*lane + 64*g];
            float4 qa = *(const float4*)&qs[d*YW + i0];
            float4 qb = *(const float4*)&qs[d*YW + i0 + 4];
            float qv[8]={qa.x,qa.y,qa.z,qa.w,qb.x,qb.y,qb.z,qb.w};
#pragma unroll
            for (int r=0;r<8;r++){
                unsigned long long qd = pk2(qv[r],qv[r]);
#pragma unroll
                for (int g=0;g<4;g++) acc[r][g]=fma2(qd,kv[g],acc[r][g]);
            }
        }
#pragma unroll
        for (int r=0;r<8;r++){
            const int i = i0+r;
            if (i >= HW) break;
            float s[8];
#pragma unroll
            for (int g=0;g<4;g++){
                upk2(acc[r][g], s[2*g], s[2*g+1]);
                int c0 = 2*lane + 64*g;
                if (c0 >= HW) { s[2*g]=-1e30f; s[2*g+1]=-1e30f; }
            }
            float mx = s[0];
#pragma unroll
            for (int k=1;k<8;k++) mx = fmaxf(mx, s[k]);
#pragma unroll
            for (int o=16;o>0;o>>=1) mx = fmaxf(mx, __shfl_xor_sync(0xffffffffu, mx, o));
            float se=0.f, pv=0.f;
#pragma unroll
            for (int g=0;g<4;g++){
                int c0 = 2*lane + 64*g;
                float e0 = __expf(s[2*g]  -mx);
                float e1 = __expf(s[2*g+1]-mx);
                se += e0+e1;
                pv += e0*vs[c0] + e1*vs[c0+1];
            }
#pragma unroll
            for (int o=16;o>0;o>>=1){
                se += __shfl_xor_sync(0xffffffffu,se,o);
                pv += __shfl_xor_sync(0xffffffffu,pv,o);
            }
            if (lane==0) g_m[n*HW+i] = 1.f/(1.f+__expf(-(pv/se)));
        }
    }
}

// ---------------------------------------------------------------------------
// Kernel 3: 32x upsample + [1-m, m]. All 32 rows of a band are identical:
// build 4 replica rows (7168B) in smem, drain band with 8 TMA bulk stores.
// grid (14, 256): blockIdx.x = cell row, blockIdx.y = n*2+ch.
// ---------------------------------------------------------------------------
__global__ __launch_bounds__(448) void k_mask(float* __restrict__ out)
{
    __shared__ __align__(16) float row[4*OUTW];   // 7168 B
    const int cr = blockIdx.x;
    const int nc = blockIdx.y;
    const int n  = nc>>1, ch = nc&1;
    const int t  = threadIdx.x;                   // 0..447

    const int rowid = t / 112, col4 = t % 112;
    float m = g_m[n*HW + cr*14 + (col4>>3)];
    float v = ch ? m : 1.f - m;
    ((float4*)row)[rowid*112 + col4] = make_float4(v,v,v,v);
    __syncthreads();

    if (t == 0){
        asm volatile("fence.proxy.async.shared::cta;" ::: "memory");
        unsigned smaddr;
        asm("{ .reg .u64 tt; cvta.to.shared.u64 tt, %1; cvt.u32.u64 %0, tt; }" : "=r"(smaddr) : "l"(row));
        float* base = out + (size_t)nc*OUTW*OUTW + (size_t)cr*32*OUTW;
#pragma unroll
        for (int rep = 0; rep < 8; rep++){
            unsigned long long gp = (unsigned long long)(base + rep*4*OUTW);
            asm volatile("cp.async.bulk.global.shared::cta.bulk_group [%0], [%1], %2;"
                         :: "l"(gp), "r"(smaddr), "r"(4*OUTW*4) : "memory");
        }
        asm volatile("cp.async.bulk.commit_group;" ::: "memory");
        asm volatile("cp.async.bulk.wait_group 0;" ::: "memory");
    }
}

// ---------------------------------------------------------------------------
extern "C" void kernel_launch(void* const* d_in, const int* in_sizes, int n_in,
                              void* d_out, int out_size)
{
    const float* x     = (const float*)d_in[0];
    const float* lam   = (const float*)d_in[1];
    const int*   index = (const int*)  d_in[2];
    const float* Wq    = (const float*)d_in[3];
    const float* bq    = (const float*)d_in[4];
    const float* Wv    = (const float*)d_in[5];
    const float* bv    = (const float*)d_in[6];

    float* out   = (float*)d_out;
    float* vtail = out + MASK_ELEMS;

    const int smem1 = (CH*ICN + 2*32*112) * (int)sizeof(float);        // 94,208 B
    const int smem2 = (ICN*YW + ICN*256 + 256) * (int)sizeof(float);   // 123,904 B
    cudaFuncSetAttribute(k_linear, cudaFuncAttributeMaxDynamicSharedMemorySize, smem1);
    cudaFuncSetAttribute(k_attn,   cudaFuncAttributeMaxDynamicSharedMemorySize, smem2);

    k_linear<<<dim3(2, NT), 224, smem1>>>(x, Wq);
    k_attn  <<<NT, 512, smem2>>>(x, Wq, bq, Wv, bv, lam, index, vtail);
    k_mask  <<<dim3(14, 256), 448>>>(out);
}

// round 8
// speedup vs baseline: 1.4900x; 1.1510x over previous
#include <cuda_runtime.h>

#define NT   128          // n*t
#define CH   256          // channels
#define HW   196          // h*w
#define ICN  64           // inter_channels
#define YW   224          // padded Y row width
#define OUTW 448
#define MASK_ELEMS (NT*2*OUTW*OUTW)

__device__ float g_Y[NT*ICN*YW];   // linear output (cols >=196 unused)
__device__ float g_m[NT*HW];
__device__ float g_Wt[CH*ICN];     // Wq transposed: [c][d]

typedef unsigned long long ull;

// ---- packed fp32x2 helpers ----
__device__ __forceinline__ ull pk2(float lo, float hi){
    ull r; asm("mov.b64 %0,{%1,%2};" : "=l"(r) : "f"(lo),"f"(hi)); return r;
}
__device__ __forceinline__ void upk2(ull v, float& lo, float& hi){
    asm("mov.b64 {%0,%1},%2;" : "=f"(lo),"=f"(hi) : "l"(v));
}
__device__ __forceinline__ ull fma2(ull a, ull b, ull c){
    ull d; asm("fma.rn.f32x2 %0,%1,%2,%3;" : "=l"(d) : "l"(a),"l"(b),"l"(c)); return d;
}

// ---------------------------------------------------------------------------
// Kernel 0: transpose Wq[64,257] -> g_Wt[256][64] (one block, one time)
// ---------------------------------------------------------------------------
__global__ __launch_bounds__(256) void k_prep(const float* __restrict__ Wq)
{
    const int t = threadIdx.x;
#pragma unroll 8
    for (int u = 0; u < 64; u++)                 // u = d, t = c
        g_Wt[t*ICN + u] = Wq[u*257 + t];
}

// ---------------------------------------------------------------------------
// Kernel 1: Y[n][d][i] = sum_c Wq[d][c]*x[n][c][i].
// grid (2,128): blockIdx.x = d-half (32 rows), blockIdx.y = n.
// 224 threads: ty = d 16-subgroup, tx = column pair {2tx, 2tx+1}.
// Per c: 16 FFMA2 + 4 broadcast LDS.128 + 1 LDG.64. 3 blocks/SM.
// ---------------------------------------------------------------------------
__global__ __launch_bounds__(224, 3) void k_linear(const float* __restrict__ x)
{
    extern __shared__ float Ws[];                 // [256][32] this d-half
    const int dh = blockIdx.x, n = blockIdx.y;
    const int tid = threadIdx.x;
    const int ty = tid / 112, tx = tid % 112;
    const int txe = (tx < 98) ? tx : 97;

    {   // coalesced smem fill from pre-transposed weights
        float4* Ws4 = (float4*)Ws;
        const float4* Wt4 = (const float4*)g_Wt;
        for (int i4 = tid; i4 < 2048; i4 += 224){
            int c = i4 >> 3, dd4 = i4 & 7;
            Ws4[c*8 + dd4] = Wt4[c*16 + dh*8 + dd4];
        }
    }
    __syncthreads();

    const float2* xb = (const float2*)(x + (size_t)n*CH*HW) + txe;  // [c][txe]

    ull acc[2][8];
#pragma unroll
    for (int q=0;q<2;q++)
#pragma unroll
        for (int p=0;p<8;p++) acc[q][p]=0ull;

    float2 xv[4];
#pragma unroll
    for (int u=0;u<4;u++) xv[u] = xb[u*98];

    for (int c = 0; c < CH; c += 4){
        float2 cur[4];
#pragma unroll
        for (int u=0;u<4;u++) cur[u]=xv[u];
        if (c < CH-4){
#pragma unroll
            for (int u=0;u<4;u++) xv[u] = xb[(size_t)(c+4+u)*98];
        }
#pragma unroll
        for (int u=0;u<4;u++){
            const ulonglong2* w = (const ulonglong2*)&Ws[(c+u)*32 + ty*16];
            ulonglong2 w0 = w[0], w1 = w[1], w2 = w[2], w3 = w[3];
            ull x0 = pk2(cur[u].x, cur[u].x);
            ull x1 = pk2(cur[u].y, cur[u].y);
            acc[0][0]=fma2(w0.x,x0,acc[0][0]); acc[1][0]=fma2(w0.x,x1,acc[1][0]);
            acc[0][1]=fma2(w0.y,x0,acc[0][1]); acc[1][1]=fma2(w0.y,x1,acc[1][1]);
            acc[0][2]=fma2(w1.x,x0,acc[0][2]); acc[1][2]=fma2(w1.x,x1,acc[1][2]);
            acc[0][3]=fma2(w1.y,x0,acc[0][3]); acc[1][3]=fma2(w1.y,x1,acc[1][3]);
            acc[0][4]=fma2(w2.x,x0,acc[0][4]); acc[1][4]=fma2(w2.x,x1,acc[1][4]);
            acc[0][5]=fma2(w2.y,x0,acc[0][5]); acc[1][5]=fma2(w2.y,x1,acc[1][5]);
            acc[0][6]=fma2(w3.x,x0,acc[0][6]); acc[1][6]=fma2(w3.x,x1,acc[1][6]);
            acc[0][7]=fma2(w3.y,x0,acc[0][7]); acc[1][7]=fma2(w3.y,x1,acc[1][7]);
        }
    }

    if (tx < 98){
        float* yb = g_Y + (size_t)n*ICN*YW + (size_t)(dh*32 + ty*16)*YW + 2*tx;
#pragma unroll
        for (int p=0;p<8;p++){
            float a,b,cc,dd;
            upk2(acc[0][p], a, cc);     // {Y[d2p][i0], Y[d2p+1][i0]}
            upk2(acc[1][p], b, dd);     // {Y[d2p][i1], Y[d2p+1][i1]}
            *(float2*)&yb[(size_t)(2*p)*YW]   = make_float2(a, b);
            *(float2*)&yb[(size_t)(2*p+1)*YW] = make_float2(cc, dd);
        }
    }
}

// ---------------------------------------------------------------------------
// Kernel 2: fused value-linear + attention + softmax + sigmoid -> g_m.
// One block/n, 512 threads (16 warps), FFMA2 score GEMM.
// ---------------------------------------------------------------------------
__global__ __launch_bounds__(512) void k_attn(const float* __restrict__ x,
                                              const float* __restrict__ Wq,
                                              const float* __restrict__ bq,
                                              const float* __restrict__ Wv,
                                              const float* __restrict__ bv,
                                              const float* __restrict__ lam,
                                              const int*   __restrict__ index,
                                              float*       __restrict__ vtail)
{
    extern __shared__ float sm[];
    float* qs = sm;               // [64][224] pre-scaled q
    float* ks = sm + ICN*YW;      // [64][256] zero-padded k
    float* vs = ks + ICN*256;     // [256] zero-padded v
    __shared__ float qadd[64], kadd[64];

    const int n = blockIdx.x, tid = threadIdx.x;
    const float lamv = lam[0] - 0.5f;
    const int sn = index[n>>3]*8 + (n&7);

    if (tid < 64) {
        float tt = Wq[tid*257+256]*lamv, b = bq[tid];
        qadd[tid] = b+tt; kadd[tid] = b-tt;
    }
    if (tid < HW) {
        const float* xb = x + (size_t)sn*CH*HW + tid;
        float a0=0.f,a1=0.f,a2=0.f,a3=0.f;
#pragma unroll 4
        for (int c=0;c<CH;c+=4){
            a0=fmaf(Wv[c  ],xb[(c  )*HW],a0);
            a1=fmaf(Wv[c+1],xb[(c+1)*HW],a1);
            a2=fmaf(Wv[c+2],xb[(c+2)*HW],a2);
            a3=fmaf(Wv[c+3],xb[(c+3)*HW],a3);
        }
        float v=(a0+a1)+(a2+a3) - Wv[CH]*lamv + bv[0];
        vs[tid]=v; vtail[n*HW+tid]=v;
    } else if (tid < 256) vs[tid]=0.f;
    __syncthreads();

    const float* Yq = g_Y + (size_t)n *ICN*YW;
    const float* Yk = g_Y + (size_t)sn*ICN*YW;
    for (int idx=tid; idx<ICN*YW; idx+=512){
        int d = idx/YW;
        qs[idx] = (Yq[idx] + qadd[d])*0.125f;     // fold 1/sqrt(64)
    }
    for (int idx=tid; idx<ICN*256; idx+=512){
        int d = idx>>8, j = idx&255;
        ks[idx] = (j<HW) ? (Yk[d*YW+j] + kadd[d]) : 0.f;
    }
    __syncthreads();

    const int warp = tid>>5, lane = tid&31;
    for (int it=0; it<2; it++){
        const int i0 = it*128 + warp*8;
        if (i0 >= HW) continue;                   // warp-uniform
        ull acc[8][4];
#pragma unroll
        for (int r=0;r<8;r++)
#pragma unroll
            for (int g=0;g<4;g++) acc[r][g]=0ull;

#pragma unroll 2
        for (int d=0; d<ICN; d++){
            ull kv[4];
#pragma unroll
            for (int g=0; g<4; g++)
                kv[g] = *(const ull*)&ks[d*256 + 2*lane + 64*g];
            float4 qa = *(const float4*)&qs[d*YW + i0];
            float4 qb = *(const float4*)&qs[d*YW + i0 + 4];
            float qv[8]={qa.x,qa.y,qa.z,qa.w,qb.x,qb.y,qb.z,qb.w};
#pragma unroll
            for (int r=0;r<8;r++){
                ull qd = pk2(qv[r],qv[r]);
#pragma unroll
                for (int g=0;g<4;g++) acc[r][g]=fma2(qd,kv[g],acc[r][g]);
            }
        }
#pragma unroll
        for (int r=0;r<8;r++){
            const int i = i0+r;
            if (i >= HW) break;
            float s[8];
#pragma unroll
            for (int g=0;g<4;g++){
                upk2(acc[r][g], s[2*g], s[2*g+1]);
                int c0 = 2*lane + 64*g;
                if (c0 >= HW) { s[2*g]=-1e30f; s[2*g+1]=-1e30f; }
            }
            float mx = s[0];
#pragma unroll
            for (int k=1;k<8;k++) mx = fmaxf(mx, s[k]);
#pragma unroll
            for (int o=16;o>0;o>>=1) mx = fmaxf(mx, __shfl_xor_sync(0xffffffffu, mx, o));
            float se=0.f, pv=0.f;
#pragma unroll
            for (int g=0;g<4;g++){
                int c0 = 2*lane + 64*g;
                float e0 = __expf(s[2*g]  -mx);
                float e1 = __expf(s[2*g+1]-mx);
                se += e0+e1;
                pv += e0*vs[c0] + e1*vs[c0+1];
            }
#pragma unroll
            for (int o=16;o>0;o>>=1){
                se += __shfl_xor_sync(0xffffffffu,se,o);
                pv += __shfl_xor_sync(0xffffffffu,pv,o);
            }
            if (lane==0) g_m[n*HW+i] = 1.f/(1.f+__expf(-(pv/se)));
        }
    }
}

// ---------------------------------------------------------------------------
// Kernel 3: 32x upsample + [1-m, m]. Build 4 replica rows (7168B) in smem,
// drain the 32-row band with 8 TMA bulk stores.
// ---------------------------------------------------------------------------
__global__ __launch_bounds__(448) void k_mask(float* __restrict__ out)
{
    __shared__ __align__(16) float row[4*OUTW];   // 7168 B
    const int cr = blockIdx.x;
    const int nc = blockIdx.y;
    const int n  = nc>>1, ch = nc&1;
    const int t  = threadIdx.x;                   // 0..447

    const int rowid = t / 112, col4 = t % 112;
    float m = g_m[n*HW + cr*14 + (col4>>3)];
    float v = ch ? m : 1.f - m;
    ((float4*)row)[rowid*112 + col4] = make_float4(v,v,v,v);
    __syncthreads();

    if (t == 0){
        asm volatile("fence.proxy.async.shared::cta;" ::: "memory");
        unsigned smaddr;
        asm("{ .reg .u64 tt; cvta.to.shared.u64 tt, %1; cvt.u32.u64 %0, tt; }" : "=r"(smaddr) : "l"(row));
        float* base = out + (size_t)nc*OUTW*OUTW + (size_t)cr*32*OUTW;
#pragma unroll
        for (int rep = 0; rep < 8; rep++){
            ull gp = (ull)(base + rep*4*OUTW);
            asm volatile("cp.async.bulk.global.shared::cta.bulk_group [%0], [%1], %2;"
                         :: "l"(gp), "r"(smaddr), "r"(4*OUTW*4) : "memory");
        }
        asm volatile("cp.async.bulk.commit_group;" ::: "memory");
        asm volatile("cp.async.bulk.wait_group 0;" ::: "memory");
    }
}

// ---------------------------------------------------------------------------
extern "C" void kernel_launch(void* const* d_in, const int* in_sizes, int n_in,
                              void* d_out, int out_size)
{
    const float* x     = (const float*)d_in[0];
    const float* lam   = (const float*)d_in[1];
    const int*   index = (const int*)  d_in[2];
    const float* Wq    = (const float*)d_in[3];
    const float* bq    = (const float*)d_in[4];
    const float* Wv    = (const float*)d_in[5];
    const float* bv    = (const float*)d_in[6];

    float* out   = (float*)d_out;
    float* vtail = out + MASK_ELEMS;

    const int smem1 = CH*32*(int)sizeof(float);                        // 32,768 B
    const int smem2 = (ICN*YW + ICN*256 + 256) * (int)sizeof(float);   // 123,904 B
    cudaFuncSetAttribute(k_linear, cudaFuncAttributeMaxDynamicSharedMemorySize, smem1);
    cudaFuncSetAttribute(k_attn,   cudaFuncAttributeMaxDynamicSharedMemorySize, smem2);

    k_prep  <<<1, 256>>>(Wq);
    k_linear<<<dim3(2, NT), 224, smem1>>>(x);
    k_attn  <<<NT, 512, smem2>>>(x, Wq, bq, Wv, bv, lam, index, vtail);
    k_mask  <<<dim3(14, 256), 448>>>(out);
}

// round 11
// speedup vs baseline: 1.5119x; 1.0148x over previous
#include <cuda_runtime.h>

#define NT   128          // n*t
#define CH   256          // channels
#define HW   196          // h*w
#define ICN  64           // inter_channels
#define YW   224          // padded Y row width
#define OUTW 448
#define MASK_ELEMS (NT*2*OUTW*OUTW)

__device__ float g_Y[NT*ICN*YW];   // linear output (cols >=196 unused)
__device__ float g_m[NT*HW];
__device__ float g_v[NT*HW];
__device__ float g_Wt[CH*ICN];     // Wq transposed: [c][d]

typedef unsigned long long ull;

// ---- packed fp32x2 helpers ----
__device__ __forceinline__ ull pk2(float lo, float hi){
    ull r; asm("mov.b64 %0,{%1,%2};" : "=l"(r) : "f"(lo),"f"(hi)); return r;
}
__device__ __forceinline__ void upk2(ull v, float& lo, float& hi){
    asm("mov.b64 {%0,%1},%2;" : "=f"(lo),"=f"(hi) : "l"(v));
}
__device__ __forceinline__ ull fma2(ull a, ull b, ull c){
    ull d; asm("fma.rn.f32x2 %0,%1,%2,%3;" : "=l"(d) : "l"(a),"l"(b),"l"(c)); return d;
}

// ---------------------------------------------------------------------------
// Kernel 0: value linear v[n][i] = Wv.x[sn][:,i] - Wv[256]*lamv + bv, plus
// vtail output; blocks 0..15 also transpose Wq -> g_Wt (1024 elems each).
// ---------------------------------------------------------------------------
__global__ __launch_bounds__(196) void k_value(const float* __restrict__ x,
                                               const float* __restrict__ Wq,
                                               const float* __restrict__ Wv,
                                               const float* __restrict__ bv,
                                               const float* __restrict__ lam,
                                               const int*   __restrict__ index,
                                               float*       __restrict__ vtail)
{
    __shared__ float wv[257];
    const int n = blockIdx.x, tid = threadIdx.x;
    for (int i = tid; i < 257; i += 196) wv[i] = Wv[i];

    // fold Wq transpose into the first 16 blocks (before k_linear runs)
    if (n < 16){
        const int base = n*1024;
        for (int j = tid; j < 1024; j += 196){
            int idx = base + j, c = idx >> 6, d = idx & 63;
            g_Wt[idx] = Wq[d*257 + c];
        }
    }
    __syncthreads();

    const int sn = index[n>>3]*8 + (n&7);
    const float* xb = x + (size_t)sn*CH*HW + tid;

    float a[8];
#pragma unroll
    for (int u=0;u<8;u++) a[u]=0.f;
#pragma unroll 4
    for (int c = 0; c < CH; c += 8){
#pragma unroll
        for (int u=0;u<8;u++)
            a[u] = fmaf(wv[c+u], xb[(size_t)(c+u)*HW], a[u]);
    }
    const float lamv = lam[0] - 0.5f;
    float v = ((a[0]+a[1])+(a[2]+a[3])) + ((a[4]+a[5])+(a[6]+a[7]))
              - wv[CH]*lamv + bv[0];
    g_v[n*HW + tid]  = v;
    vtail[n*HW + tid] = v;
}

// ---------------------------------------------------------------------------
// Kernel 1: Y[n][d][i] = sum_c Wq[d][c]*x[n][c][i].
// grid (2,128): blockIdx.x = d-half (32 rows), blockIdx.y = n.
// 224 threads: ty = d 16-subgroup, tx = column pair. MLP-8 x prefetch.
// ---------------------------------------------------------------------------
__global__ __launch_bounds__(224, 3) void k_linear(const float* __restrict__ x)
{
    extern __shared__ float Ws[];                 // [256][32] this d-half
    const int dh = blockIdx.x, n = blockIdx.y;
    const int tid = threadIdx.x;
    const int ty = tid / 112, tx = tid % 112;
    const int txe = (tx < 98) ? tx : 97;

    {   // coalesced smem fill from pre-transposed weights
        float4* Ws4 = (float4*)Ws;
        const float4* Wt4 = (const float4*)g_Wt;
        for (int i4 = tid; i4 < 2048; i4 += 224){
            int c = i4 >> 3, dd4 = i4 & 7;
            Ws4[c*8 + dd4] = Wt4[c*16 + dh*8 + dd4];
        }
    }
    __syncthreads();

    const float2* xb = (const float2*)(x + (size_t)n*CH*HW) + txe;  // [c][txe]

    ull acc[2][8];
#pragma unroll
    for (int q=0;q<2;q++)
#pragma unroll
        for (int p=0;p<8;p++) acc[q][p]=0ull;

    float2 xv[8];
#pragma unroll
    for (int u=0;u<8;u++) xv[u] = xb[(size_t)u*98];

    for (int c = 0; c < CH; c += 8){
        float2 cur[8];
#pragma unroll
        for (int u=0;u<8;u++) cur[u]=xv[u];
        if (c < CH-8){
#pragma unroll
            for (int u=0;u<8;u++) xv[u] = xb[(size_t)(c+8+u)*98];
        }
#pragma unroll
        for (int u=0;u<8;u++){
            const ulonglong2* w = (const ulonglong2*)&Ws[(c+u)*32 + ty*16];
            ulonglong2 w0 = w[0], w1 = w[1], w2 = w[2], w3 = w[3];
            ull x0 = pk2(cur[u].x, cur[u].x);
            ull x1 = pk2(cur[u].y, cur[u].y);
            acc[0][0]=fma2(w0.x,x0,acc[0][0]); acc[1][0]=fma2(w0.x,x1,acc[1][0]);
            acc[0][1]=fma2(w0.y,x0,acc[0][1]); acc[1][1]=fma2(w0.y,x1,acc[1][1]);
            acc[0][2]=fma2(w1.x,x0,acc[0][2]); acc[1][2]=fma2(w1.x,x1,acc[1][2]);
            acc[0][3]=fma2(w1.y,x0,acc[0][3]); acc[1][3]=fma2(w1.y,x1,acc[1][3]);
            acc[0][4]=fma2(w2.x,x0,acc[0][4]); acc[1][4]=fma2(w2.x,x1,acc[1][4]);
            acc[0][5]=fma2(w2.y,x0,acc[0][5]); acc[1][5]=fma2(w2.y,x1,acc[1][5]);
            acc[0][6]=fma2(w3.x,x0,acc[0][6]); acc[1][6]=fma2(w3.x,x1,acc[1][6]);
            acc[0][7]=fma2(w3.y,x0,acc[0][7]); acc[1][7]=fma2(w3.y,x1,acc[1][7]);
        }
    }

    if (tx < 98){
        float* yb = g_Y + (size_t)n*ICN*YW + (size_t)(dh*32 + ty*16)*YW + 2*tx;
#pragma unroll
        for (int p=0;p<8;p++){
            float a,b,cc,dd;
            upk2(acc[0][p], a, cc);
            upk2(acc[1][p], b, dd);
            *(float2*)&yb[(size_t)(2*p)*YW]   = make_float2(a, b);
            *(float2*)&yb[(size_t)(2*p+1)*YW] = make_float2(cc, dd);
        }
    }
}

// ---------------------------------------------------------------------------
// Kernel 2: attention + softmax + sigmoid -> g_m (value precomputed in g_v).
// One block/n, 512 threads (16 warps), FFMA2 score GEMM.
// ---------------------------------------------------------------------------
__global__ __launch_bounds__(512) void k_attn(const float* __restrict__ Wq,
                                              const float* __restrict__ bq,
                                              const float* __restrict__ lam,
                                              const int*   __restrict__ index)
{
    extern __shared__ float sm[];
    float* qs = sm;               // [64][224] pre-scaled q
    float* ks = sm + ICN*YW;      // [64][256] zero-padded k
    float* vs = ks + ICN*256;     // [256] zero-padded v
    __shared__ float qadd[64], kadd[64];

    const int n = blockIdx.x, tid = threadIdx.x;
    const float lamv = lam[0] - 0.5f;
    const int sn = index[n>>3]*8 + (n&7);

    if (tid < 64) {
        float tt = Wq[tid*257+256]*lamv, b = bq[tid];
        qadd[tid] = b+tt; kadd[tid] = b-tt;
    }
    if (tid < 256) vs[tid] = (tid < HW) ? g_v[n*HW + tid] : 0.f;
    __syncthreads();

    const float* Yq = g_Y + (size_t)n *ICN*YW;
    const float* Yk = g_Y + (size_t)sn*ICN*YW;
    for (int idx=tid; idx<ICN*YW; idx+=512){
        int d = idx/YW;
        qs[idx] = (Yq[idx] + qadd[d])*0.125f;     // fold 1/sqrt(64)
    }
    for (int idx=tid; idx<ICN*256; idx+=512){
        int d = idx>>8, j = idx&255;
        ks[idx] = (j<HW) ? (Yk[d*YW+j] + kadd[d]) : 0.f;
    }
    __syncthreads();

    const int warp = tid>>5, lane = tid&31;
    for (int it=0; it<2; it++){
        const int i0 = it*128 + warp*8;
        if (i0 >= HW) continue;                   // warp-uniform
        ull acc[8][4];
#pragma unroll
        for (int r=0;r<8;r++)
#pragma unroll
            for (int g=0;g<4;g++) acc[r][g]=0ull;

#pragma unroll 2
        for (int d=0; d<ICN; d++){
            ull kv[4];
#pragma unroll
            for (int g=0; g<4; g++)
                kv[g] = *(const ull*)&ks[d*256 + 2*lane + 64*g];
            float4 qa = *(const float4*)&qs[d*YW + i0];
            float4 qb = *(const float4*)&qs[d*YW + i0 + 4];
            float qv[8]={qa.x,qa.y,qa.z,qa.w,qb.x,qb.y,qb.z,qb.w};
#pragma unroll
            for (int r=0;r<8;r++){
                ull qd = pk2(qv[r],qv[r]);
#pragma unroll
                for (int g=0;g<4;g++) acc[r][g]=fma2(qd,kv[g],acc[r][g]);
            }
        }
#pragma unroll
        for (int r=0;r<8;r++){
            const int i = i0+r;
            if (i >= HW) break;
            float s[8];
#pragma unroll
            for (int g=0;g<4;g++){
                upk2(acc[r][g], s[2*g], s[2*g+1]);
                int c0 = 2*lane + 64*g;
                if (c0 >= HW) { s[2*g]=-1e30f; s[2*g+1]=-1e30f; }
            }
            float mx = s[0];
#pragma unroll
            for (int k=1;k<8;k++) mx = fmaxf(mx, s[k]);
#pragma unroll
            for (int o=16;o>0;o>>=1) mx = fmaxf(mx, __shfl_xor_sync(0xffffffffu, mx, o));
            float se=0.f, pv=0.f;
#pragma unroll
            for (int g=0;g<4;g++){
                int c0 = 2*lane + 64*g;
                float e0 = __expf(s[2*g]  -mx);
                float e1 = __expf(s[2*g+1]-mx);
                se += e0+e1;
                pv += e0*vs[c0] + e1*vs[c0+1];
            }
#pragma unroll
            for (int o=16;o>0;o>>=1){
                se += __shfl_xor_sync(0xffffffffu,se,o);
                pv += __shfl_xor_sync(0xffffffffu,pv,o);
            }
            if (lane==0) g_m[n*HW+i] = 1.f/(1.f+__expf(-(pv/se)));
        }
    }
}

// ---------------------------------------------------------------------------
// Kernel 3: 32x upsample + [1-m, m]. Build 8 replica rows (14336B = 896
// float4) in smem, drain the 32-row band with 4 TMA bulk stores.
// ---------------------------------------------------------------------------
__global__ __launch_bounds__(448) void k_mask(float* __restrict__ out)
{
    __shared__ __align__(16) float row[8*OUTW];   // 14336 B = 896 float4
    __shared__ float rv[14];
    const int cr = blockIdx.x;
    const int nc = blockIdx.y;
    const int n  = nc>>1, ch = nc&1;
    const int t  = threadIdx.x;                   // 0..447

    if (t < 14){
        float m = g_m[n*HW + cr*14 + t];
        rv[t] = ch ? m : 1.f - m;
    }
    __syncthreads();
    float4* b4 = (float4*)row;
#pragma unroll
    for (int u=0; u<2; u++){                      // 2*448 = 896 float4 total
        const int idx  = t + 448*u;
        const int col4 = idx % 112;
        const float v  = rv[col4>>3];
        b4[idx] = make_float4(v,v,v,v);
    }
    __syncthreads();

    if (t == 0){
        asm volatile("fence.proxy.async.shared::cta;" ::: "memory");
        unsigned smaddr;
        asm("{ .reg .u64 tt; cvta.to.shared.u64 tt, %1; cvt.u32.u64 %0, tt; }" : "=r"(smaddr) : "l"(row));
        float* base = out + (size_t)nc*OUTW*OUTW + (size_t)cr*32*OUTW;
#pragma unroll
        for (int rep = 0; rep < 4; rep++){
            ull gp = (ull)(base + rep*8*OUTW);
            asm volatile("cp.async.bulk.global.shared::cta.bulk_group [%0], [%1], %2;"
                         :: "l"(gp), "r"(smaddr), "r"(8*OUTW*4) : "memory");
        }
        asm volatile("cp.async.bulk.commit_group;" ::: "memory");
        asm volatile("cp.async.bulk.wait_group 0;" ::: "memory");
    }
}

// ---------------------------------------------------------------------------
extern "C" void kernel_launch(void* const* d_in, const int* in_sizes, int n_in,
                              void* d_out, int out_size)
{
    const float* x     = (const float*)d_in[0];
    const float* lam   = (const float*)d_in[1];
    const int*   index = (const int*)  d_in[2];
    const float* Wq    = (const float*)d_in[3];
    const float* bq    = (const float*)d_in[4];
    const float* Wv    = (const float*)d_in[5];
    const float* bv    = (const float*)d_in[6];

    float* out   = (float*)d_out;
    float* vtail = out + MASK_ELEMS;

    const int smem1 = CH*32*(int)sizeof(float);                        // 32,768 B
    const int smem2 = (ICN*YW + ICN*256 + 256) * (int)sizeof(float);   // 123,904 B
    cudaFuncSetAttribute(k_linear, cudaFuncAttributeMaxDynamicSharedMemorySize, smem1);
    cudaFuncSetAttribute(k_attn,   cudaFuncAttributeMaxDynamicSharedMemorySize, smem2);

    k_value <<<NT, 196>>>(x, Wq, Wv, bv, lam, index, vtail);
    k_linear<<<dim3(2, NT), 224, smem1>>>(x);
    k_attn  <<<NT, 512, smem2>>>(Wq, bq, lam, index);
    k_mask  <<<dim3(14, 256), 448>>>(out);
}